// round 1
// baseline (speedup 1.0000x reference)
#include <cuda_runtime.h>
#include <cuda_bf16.h>

// Problem constants
#define NB 8
#define HH 64
#define WW 64
#define DIM 768
#define RR 16
#define NPIX (NB * HH * WW)        // 32768
#define MOUT (3 * DIM)             // 2304

// Scratch (device globals: allocation-free)
__device__ float g_aq[NPIX * RR];
__device__ float g_av[NPIX * RR];
__device__ float g_mq[NPIX * RR];
__device__ float g_mv[NPIX * RR];

// ---------------------------------------------------------------------------
// Kernel 1: a_q = x @ Wa_q, a_v = x @ Wa_v   ([32768,768] @ [768,16])
// Block: 256 threads = 8 warps; each warp handles one row; lane<16 -> q col,
// lane>=16 -> v col. x rows staged in shared (broadcast reads).
// ---------------------------------------------------------------------------
__global__ void k_down(const float* __restrict__ x,
                       const float* __restrict__ Wa_q,
                       const float* __restrict__ Wa_v) {
    __shared__ float sx[8][DIM];
    const int row0 = blockIdx.x * 8;

    // cooperative load 8 rows (8*768 floats) with float4
    const float4* xv = (const float4*)(x + (size_t)row0 * DIM);
    float4* sxv = (float4*)&sx[0][0];
    #pragma unroll
    for (int i = threadIdx.x; i < 8 * DIM / 4; i += 256) sxv[i] = xv[i];
    __syncthreads();

    const int warp = threadIdx.x >> 5;
    const int lane = threadIdx.x & 31;
    const int row  = row0 + warp;
    const int j    = lane & 15;
    const float* __restrict__ Wa = (lane < 16) ? Wa_q : Wa_v;
    const float* sr = sx[warp];

    float acc = 0.f;
    #pragma unroll 8
    for (int k = 0; k < DIM; k++)
        acc += sr[k] * __ldg(&Wa[k * RR + j]);

    float* out = (lane < 16) ? g_aq : g_av;
    out[row * RR + j] = acc;
}

// ---------------------------------------------------------------------------
// Kernel 2: mid = conv3x3(a,K3)+b3 + conv1x1(a,K1)+b1 + a   (NHWC, SAME)
// grid: (W/16, (H/16)*B, 2)  block: 256 (16x16 pixels)
// ---------------------------------------------------------------------------
__global__ void k_conv(const float* __restrict__ K_q3, const float* __restrict__ b_q3,
                       const float* __restrict__ K_v3, const float* __restrict__ b_v3,
                       const float* __restrict__ K_q1, const float* __restrict__ b_q1,
                       const float* __restrict__ K_v1, const float* __restrict__ b_v1) {
    __shared__ float sh[18 * 18 * 17];   // [hh][ww][c], channel pitch 17 (conflict-free)
    __shared__ float sK3[9 * RR * RR];
    __shared__ float sK1[RR * RR];
    __shared__ float sb[RR];

    const int qv = blockIdx.z;
    const float* __restrict__ a  = qv == 0 ? g_aq : g_av;
    const float* __restrict__ K3 = qv == 0 ? K_q3 : K_v3;
    const float* __restrict__ K1 = qv == 0 ? K_q1 : K_v1;
    const float* __restrict__ b3 = qv == 0 ? b_q3 : b_v3;
    const float* __restrict__ b1 = qv == 0 ? b_q1 : b_v1;
    float* __restrict__ mid = qv == 0 ? g_mq : g_mv;

    const int tile_x = blockIdx.x * 16;
    const int img    = blockIdx.y >> 2;
    const int tile_y = (blockIdx.y & 3) * 16;
    const int tid = threadIdx.x;

    for (int i = tid; i < 9 * RR * RR; i += 256) sK3[i] = K3[i];
    for (int i = tid; i < RR * RR; i += 256) sK1[i] = K1[i];
    if (tid < RR) sb[tid] = b3[tid] + b1[tid];

    // halo load: 18x18x16 with zero padding outside image
    for (int i = tid; i < 18 * 18 * 16; i += 256) {
        int c = i & 15;
        int p = i >> 4;
        int ww = p % 18, hh = p / 18;
        int h = tile_y + hh - 1, w = tile_x + ww - 1;
        float v = 0.f;
        if (h >= 0 && h < HH && w >= 0 && w < WW)
            v = a[(((img * HH + h) * WW) + w) * RR + c];
        sh[(hh * 18 + ww) * 17 + c] = v;
    }
    __syncthreads();

    const int ty = tid >> 4, tx = tid & 15;
    float acc[RR];
    const float* center = &sh[((ty + 1) * 18 + (tx + 1)) * 17];
    #pragma unroll
    for (int co = 0; co < RR; co++) acc[co] = sb[co] + center[co];   // bias + identity

    // 1x1 conv
    #pragma unroll
    for (int ci = 0; ci < RR; ci++) {
        float v = center[ci];
        #pragma unroll
        for (int co = 0; co < RR; co++) acc[co] += v * sK1[ci * RR + co];
    }
    // 3x3 conv
    #pragma unroll
    for (int kh = 0; kh < 3; kh++) {
        #pragma unroll
        for (int kw = 0; kw < 3; kw++) {
            const float* p  = &sh[((ty + kh) * 18 + (tx + kw)) * 17];
            const float* kk = &sK3[(kh * 3 + kw) * RR * RR];
            #pragma unroll
            for (int ci = 0; ci < RR; ci++) {
                float v = p[ci];
                #pragma unroll
                for (int co = 0; co < RR; co++) acc[co] += v * kk[ci * RR + co];
            }
        }
    }

    const int h = tile_y + ty, w = tile_x + tx;
    float* o = &mid[(((img * HH + h) * WW) + w) * RR];
    #pragma unroll
    for (int co = 0; co < RR; co += 4)
        *(float4*)&o[co] = make_float4(acc[co], acc[co + 1], acc[co + 2], acc[co + 3]);
}

// ---------------------------------------------------------------------------
// Kernel 3: out = x @ W_qkv + b_qkv  (+ mid_q @ Wb_q on cols [0,768),
//                                     + mid_v @ Wb_v on cols [1536,2304))
// 128x128 block tile, BK=8, 256 threads, 8x8 micro-tile.
// Low-rank term fused as 2 extra K-blocks (K=16) for the relevant col tiles.
// ---------------------------------------------------------------------------
__global__ void __launch_bounds__(256, 2)
k_gemm(const float* __restrict__ x, const float* __restrict__ Wqkv,
       const float* __restrict__ bqkv,
       const float* __restrict__ Wb_q, const float* __restrict__ Wb_v,
       float* __restrict__ out) {
    __shared__ float As[8][128];   // [k][n]
    __shared__ float Bs[8][128];   // [k][m]

    const int n0 = blockIdx.y * 128;
    const int m0 = blockIdx.x * 128;
    const int tid = threadIdx.x;

    const int a_r = tid >> 1;             // 0..127
    const int a_c = (tid & 1) * 4;        // 0 or 4
    const int b_r = tid >> 5;             // 0..7
    const int b_c = (tid & 31) * 4;       // 0..124
    const int tx = tid & 15, ty = tid >> 4;

    float acc[8][8];
    #pragma unroll
    for (int i = 0; i < 8; i++)
        #pragma unroll
        for (int j = 0; j < 8; j++) acc[i][j] = 0.f;

    const float* Aptr = x + (size_t)(n0 + a_r) * DIM + a_c;
    const float* Bptr = Wqkv + (size_t)b_r * MOUT + m0 + b_c;

    for (int kb = 0; kb < DIM / 8; kb++) {
        float4 av = *(const float4*)(Aptr + kb * 8);
        float4 bv = *(const float4*)(Bptr + (size_t)kb * 8 * MOUT);
        As[a_c + 0][a_r] = av.x;
        As[a_c + 1][a_r] = av.y;
        As[a_c + 2][a_r] = av.z;
        As[a_c + 3][a_r] = av.w;
        *(float4*)&Bs[b_r][b_c] = bv;
        __syncthreads();

        #pragma unroll
        for (int k = 0; k < 8; k++) {
            float ar[8], br[8];
            *(float4*)&ar[0] = *(const float4*)&As[k][ty * 8];
            *(float4*)&ar[4] = *(const float4*)&As[k][ty * 8 + 4];
            *(float4*)&br[0] = *(const float4*)&Bs[k][tx * 8];
            *(float4*)&br[4] = *(const float4*)&Bs[k][tx * 8 + 4];
            #pragma unroll
            for (int i = 0; i < 8; i++)
                #pragma unroll
                for (int j = 0; j < 8; j++) acc[i][j] += ar[i] * br[j];
        }
        __syncthreads();
    }

    // fused low-rank epilogue (K=16 as 2 extra K-blocks)
    const int region = (m0 + 128 <= DIM) ? 0 : (m0 >= 2 * DIM ? 1 : -1);
    if (region >= 0) {
        const float* __restrict__ midp = region == 0 ? g_mq : g_mv;
        const float* __restrict__ Wb   = region == 0 ? Wb_q : Wb_v;
        const int mo = m0 - (region == 0 ? 0 : 2 * DIM);
        #pragma unroll
        for (int kb = 0; kb < 2; kb++) {
            float4 av = *(const float4*)(midp + (size_t)(n0 + a_r) * RR + kb * 8 + a_c);
            float4 bv = *(const float4*)(Wb + (size_t)(kb * 8 + b_r) * DIM + mo + b_c);
            As[a_c + 0][a_r] = av.x;
            As[a_c + 1][a_r] = av.y;
            As[a_c + 2][a_r] = av.z;
            As[a_c + 3][a_r] = av.w;
            *(float4*)&Bs[b_r][b_c] = bv;
            __syncthreads();

            #pragma unroll
            for (int k = 0; k < 8; k++) {
                float ar[8], br[8];
                *(float4*)&ar[0] = *(const float4*)&As[k][ty * 8];
                *(float4*)&ar[4] = *(const float4*)&As[k][ty * 8 + 4];
                *(float4*)&br[0] = *(const float4*)&Bs[k][tx * 8];
                *(float4*)&br[4] = *(const float4*)&Bs[k][tx * 8 + 4];
                #pragma unroll
                for (int i = 0; i < 8; i++)
                    #pragma unroll
                    for (int j = 0; j < 8; j++) acc[i][j] += ar[i] * br[j];
            }
            __syncthreads();
        }
    }

    // bias + store
    float bias[8];
    #pragma unroll
    for (int j = 0; j < 8; j++) bias[j] = __ldg(&bqkv[m0 + tx * 8 + j]);

    #pragma unroll
    for (int i = 0; i < 8; i++) {
        const int n = n0 + ty * 8 + i;
        float* o = out + (size_t)n * MOUT + m0 + tx * 8;
        float4 v0 = make_float4(acc[i][0] + bias[0], acc[i][1] + bias[1],
                                acc[i][2] + bias[2], acc[i][3] + bias[3]);
        float4 v1 = make_float4(acc[i][4] + bias[4], acc[i][5] + bias[5],
                                acc[i][6] + bias[6], acc[i][7] + bias[7]);
        *(float4*)&o[0] = v0;
        *(float4*)&o[4] = v1;
    }
}

// ---------------------------------------------------------------------------
extern "C" void kernel_launch(void* const* d_in, const int* in_sizes, int n_in,
                              void* d_out, int out_size) {
    const float* x     = (const float*)d_in[0];
    const float* W_qkv = (const float*)d_in[1];
    const float* b_qkv = (const float*)d_in[2];
    const float* Wa_q  = (const float*)d_in[3];
    const float* Wb_q  = (const float*)d_in[4];
    const float* Wa_v  = (const float*)d_in[5];
    const float* Wb_v  = (const float*)d_in[6];
    const float* K_q3  = (const float*)d_in[7];
    const float* b_q3  = (const float*)d_in[8];
    const float* K_v3  = (const float*)d_in[9];
    const float* b_v3  = (const float*)d_in[10];
    const float* K_q1  = (const float*)d_in[11];
    const float* b_q1  = (const float*)d_in[12];
    const float* K_v1  = (const float*)d_in[13];
    const float* b_v1  = (const float*)d_in[14];
    float* out = (float*)d_out;

    k_down<<<NPIX / 8, 256>>>(x, Wa_q, Wa_v);
    k_conv<<<dim3(WW / 16, (HH / 16) * NB, 2), 256>>>(K_q3, b_q3, K_v3, b_v3,
                                                      K_q1, b_q1, K_v1, b_v1);
    k_gemm<<<dim3(MOUT / 128, NPIX / 128), 256>>>(x, W_qkv, b_qkv, Wb_q, Wb_v, out);
}

// round 3
// speedup vs baseline: 1.9922x; 1.9922x over previous
#include <cuda_runtime.h>
#include <cuda_bf16.h>
#include <cstdint>

#define NB 8
#define HH 64
#define WW 64
#define DIM 768
#define RR 16
#define NPIX 32768
#define MOUT 2304
#define KPAD 64

#define STAGES 4
#define APITCH 40                        // bf16 elems per smem row (32 data + 8 pad)
#define STAGE_A_BYTES (128 * APITCH * 2) // 10240
#define STAGE_BYTES (2 * STAGE_A_BYTES)  // 20480
#define SMEM_TOTAL (STAGES * STAGE_BYTES)

// ------------------------- scratch (device globals) -------------------------
__device__ __nv_bfloat16 g_xhi[NPIX * DIM];
__device__ __nv_bfloat16 g_xlo[NPIX * DIM];
__device__ __nv_bfloat16 g_wthi[MOUT * DIM];   // W_qkv transposed [n][k]
__device__ __nv_bfloat16 g_wtlo[MOUT * DIM];
__device__ float g_aq[NPIX * RR];
__device__ float g_av[NPIX * RR];
__device__ __nv_bfloat16 g_mqhi[NPIX * KPAD];  // mid_q padded K 16->64
__device__ __nv_bfloat16 g_mqlo[NPIX * KPAD];
__device__ __nv_bfloat16 g_mvhi[NPIX * KPAD];
__device__ __nv_bfloat16 g_mvlo[NPIX * KPAD];
__device__ __nv_bfloat16 g_wbtq_hi[DIM * KPAD]; // Wb_q transposed+padded [n][k]
__device__ __nv_bfloat16 g_wbtq_lo[DIM * KPAD];
__device__ __nv_bfloat16 g_wbtv_hi[DIM * KPAD];
__device__ __nv_bfloat16 g_wbtv_lo[DIM * KPAD];

// ------------------------------ helpers -------------------------------------
__device__ __forceinline__ void split2(float v, __nv_bfloat16& h, __nv_bfloat16& l) {
    h = __float2bfloat16(v);
    l = __float2bfloat16(v - __bfloat162float(h));
}

__device__ __forceinline__ uint32_t smem_u32(const void* p) {
    uint32_t a;
    asm("{ .reg .u64 t; cvta.to.shared.u64 t, %1; cvt.u32.u64 %0, t; }" : "=r"(a) : "l"(p));
    return a;
}

__device__ __forceinline__ void cp16(uint32_t dst, const void* src) {
    asm volatile("cp.async.cg.shared.global [%0], [%1], 16;" :: "r"(dst), "l"(src));
}

__device__ __forceinline__ void ldm_x4(uint32_t addr, uint32_t& r0, uint32_t& r1,
                                       uint32_t& r2, uint32_t& r3) {
    asm volatile("ldmatrix.sync.aligned.m8n8.x4.shared.b16 {%0,%1,%2,%3}, [%4];"
                 : "=r"(r0), "=r"(r1), "=r"(r2), "=r"(r3) : "r"(addr));
}

__device__ __forceinline__ void mma16816(float* c, const uint32_t* a, const uint32_t* b) {
    asm volatile(
        "mma.sync.aligned.m16n8k16.row.col.f32.bf16.bf16.f32 "
        "{%0,%1,%2,%3}, {%4,%5,%6,%7}, {%8,%9}, {%0,%1,%2,%3};"
        : "+f"(c[0]), "+f"(c[1]), "+f"(c[2]), "+f"(c[3])
        : "r"(a[0]), "r"(a[1]), "r"(a[2]), "r"(a[3]), "r"(b[0]), "r"(b[1]));
}

// ---------------------------------------------------------------------------
// x -> hi/lo bf16
// ---------------------------------------------------------------------------
__global__ void k_split_x(const float* __restrict__ x) {
    size_t i = (size_t)blockIdx.x * 256 + threadIdx.x; // one uint4 (8 bf16) out
    const float4* xv = (const float4*)x;
    float4 a = xv[2 * i], b = xv[2 * i + 1];
    float v[8] = {a.x, a.y, a.z, a.w, b.x, b.y, b.z, b.w};
    __nv_bfloat16 h[8], l[8];
    #pragma unroll
    for (int j = 0; j < 8; j++) split2(v[j], h[j], l[j]);
    ((uint4*)g_xhi)[i] = *(uint4*)h;
    ((uint4*)g_xlo)[i] = *(uint4*)l;
}

// ---------------------------------------------------------------------------
// W_qkv [768][2304] -> transposed hi/lo bf16 [2304][768]
// ---------------------------------------------------------------------------
__global__ void k_split_w(const float* __restrict__ W) {
    __shared__ float t[32][33];
    const int bx = blockIdx.x;           // over MOUT/32 = 72
    const int by = blockIdx.y;           // over DIM/32 = 24
    const int tx = threadIdx.x & 31, ty = threadIdx.x >> 5;
    #pragma unroll
    for (int k = 0; k < 4; k++) {
        int r = by * 32 + ty + k * 8;
        t[ty + k * 8][tx] = W[(size_t)r * MOUT + bx * 32 + tx];
    }
    __syncthreads();
    #pragma unroll
    for (int k = 0; k < 4; k++) {
        int n = bx * 32 + ty + k * 8;
        float v = t[tx][ty + k * 8];
        __nv_bfloat16 h, l;
        split2(v, h, l);
        g_wthi[(size_t)n * DIM + by * 32 + tx] = h;
        g_wtlo[(size_t)n * DIM + by * 32 + tx] = l;
    }
}

// ---------------------------------------------------------------------------
// Wb [16][768] -> transposed padded hi/lo [768][64]
// ---------------------------------------------------------------------------
__global__ void k_split_wb(const float* __restrict__ Wb_q,
                           const float* __restrict__ Wb_v) {
    const int qv = blockIdx.y;
    const float* Wb = qv ? Wb_v : Wb_q;
    __nv_bfloat16* oh = qv ? g_wbtv_hi : g_wbtq_hi;
    __nv_bfloat16* ol = qv ? g_wbtv_lo : g_wbtq_lo;
    int i = blockIdx.x * 256 + threadIdx.x;   // DIM*KPAD = 49152
    int n = i >> 6, k = i & 63;
    float v = (k < RR) ? Wb[k * DIM + n] : 0.f;
    __nv_bfloat16 h, l;
    split2(v, h, l);
    oh[i] = h;
    ol[i] = l;
}

// ---------------------------------------------------------------------------
// a_q = x @ Wa_q, a_v = x @ Wa_v  -- tiled, 32 rows x 32 cols per block
// ---------------------------------------------------------------------------
__global__ void k_down(const float* __restrict__ x,
                       const float* __restrict__ Wa_q,
                       const float* __restrict__ Wa_v) {
    __shared__ float sx[32][64];
    __shared__ float sW[64][32];
    const int row0 = blockIdx.x * 32;
    const int tid = threadIdx.x;
    const int r = tid >> 3, c0 = (tid & 7) * 4;
    float acc[4] = {0.f, 0.f, 0.f, 0.f};

    for (int kb = 0; kb < DIM / 64; kb++) {
        #pragma unroll
        for (int t = tid; t < 512; t += 256) {
            int rr = t >> 4, cc = (t & 15) * 4;
            *(float4*)&sx[rr][cc] =
                *(const float4*)&x[(size_t)(row0 + rr) * DIM + kb * 64 + cc];
        }
        #pragma unroll
        for (int t = tid; t < 2048; t += 256) {
            int kk = t >> 5, cc = t & 31;
            sW[kk][cc] = (cc < 16) ? Wa_q[(kb * 64 + kk) * RR + cc]
                                   : Wa_v[(kb * 64 + kk) * RR + (cc - 16)];
        }
        __syncthreads();
        #pragma unroll 16
        for (int k = 0; k < 64; k++) {
            float xv = sx[r][k];
            float4 w = *(float4*)&sW[k][c0];
            acc[0] += xv * w.x; acc[1] += xv * w.y;
            acc[2] += xv * w.z; acc[3] += xv * w.w;
        }
        __syncthreads();
    }
    const int row = row0 + r;
    if (c0 < 16) *(float4*)&g_aq[row * RR + c0] = *(float4*)acc;
    else         *(float4*)&g_av[row * RR + (c0 - 16)] = *(float4*)acc;
}

// ---------------------------------------------------------------------------
// mid = conv3x3 + b3 + conv1x1 + b1 + identity; output split hi/lo, K-padded
// ---------------------------------------------------------------------------
__global__ void k_conv(const float* __restrict__ K_q3, const float* __restrict__ b_q3,
                       const float* __restrict__ K_v3, const float* __restrict__ b_v3,
                       const float* __restrict__ K_q1, const float* __restrict__ b_q1,
                       const float* __restrict__ K_v1, const float* __restrict__ b_v1) {
    __shared__ float sh[18 * 18 * 17];
    __shared__ float sK3[9 * RR * RR];
    __shared__ float sK1[RR * RR];
    __shared__ float sb[RR];

    const int qv = blockIdx.z;
    const float* __restrict__ a  = qv == 0 ? g_aq : g_av;
    const float* __restrict__ K3 = qv == 0 ? K_q3 : K_v3;
    const float* __restrict__ K1 = qv == 0 ? K_q1 : K_v1;
    const float* __restrict__ b3 = qv == 0 ? b_q3 : b_v3;
    const float* __restrict__ b1 = qv == 0 ? b_q1 : b_v1;
    __nv_bfloat16* __restrict__ mh = qv == 0 ? g_mqhi : g_mvhi;
    __nv_bfloat16* __restrict__ ml = qv == 0 ? g_mqlo : g_mvlo;

    const int tile_x = blockIdx.x * 16;
    const int img    = blockIdx.y >> 2;
    const int tile_y = (blockIdx.y & 3) * 16;
    const int tid = threadIdx.x;

    for (int i = tid; i < 9 * RR * RR; i += 256) sK3[i] = K3[i];
    for (int i = tid; i < RR * RR; i += 256) sK1[i] = K1[i];
    if (tid < RR) sb[tid] = b3[tid] + b1[tid];

    for (int i = tid; i < 18 * 18 * 16; i += 256) {
        int c = i & 15;
        int p = i >> 4;
        int ww = p % 18, hh = p / 18;
        int h = tile_y + hh - 1, w = tile_x + ww - 1;
        float v = 0.f;
        if (h >= 0 && h < HH && w >= 0 && w < WW)
            v = a[(((img * HH + h) * WW) + w) * RR + c];
        sh[(hh * 18 + ww) * 17 + c] = v;
    }
    __syncthreads();

    const int ty = tid >> 4, tx = tid & 15;
    float acc[RR];
    const float* center = &sh[((ty + 1) * 18 + (tx + 1)) * 17];
    #pragma unroll
    for (int co = 0; co < RR; co++) acc[co] = sb[co] + center[co];

    #pragma unroll
    for (int ci = 0; ci < RR; ci++) {
        float v = center[ci];
        #pragma unroll
        for (int co = 0; co < RR; co++) acc[co] += v * sK1[ci * RR + co];
    }
    #pragma unroll
    for (int kh = 0; kh < 3; kh++) {
        #pragma unroll
        for (int kw = 0; kw < 3; kw++) {
            const float* p  = &sh[((ty + kh) * 18 + (tx + kw)) * 17];
            const float* kk = &sK3[(kh * 3 + kw) * RR * RR];
            #pragma unroll
            for (int ci = 0; ci < RR; ci++) {
                float v = p[ci];
                #pragma unroll
                for (int co = 0; co < RR; co++) acc[co] += v * kk[ci * RR + co];
            }
        }
    }

    const int h = tile_y + ty, w = tile_x + tx;
    const int pix = ((img * HH + h) * WW) + w;
    __nv_bfloat16 hb[RR], lb[RR];
    #pragma unroll
    for (int co = 0; co < RR; co++) split2(acc[co], hb[co], lb[co]);
    uint4* oh = (uint4*)(mh + (size_t)pix * KPAD);
    uint4* ol = (uint4*)(ml + (size_t)pix * KPAD);
    oh[0] = ((uint4*)hb)[0]; oh[1] = ((uint4*)hb)[1];
    ol[0] = ((uint4*)lb)[0]; ol[1] = ((uint4*)lb)[1];
    uint4 z = make_uint4(0, 0, 0, 0);
    #pragma unroll
    for (int t = 2; t < 8; t++) { oh[t] = z; ol[t] = z; }
}

// ---------------------------------------------------------------------------
// Main HMMA GEMM: out[32768,2304] = split-bf16(x) @ split-bf16(W^T) + LoRA + bias
// 128x128 tile, BK=32, 4-stage cp.async pipeline, 8 warps (64x32 warp tiles).
// Flat job loop: 3 passes (hi*hi, hi*lo, lo*hi) x (24 chunks + 2 LoRA chunks).
// ---------------------------------------------------------------------------
__global__ void __launch_bounds__(256) k_mma(const float* __restrict__ bqkv,
                                             float* __restrict__ out) {
    extern __shared__ char smem[];
    const uint32_t sbase = smem_u32(smem);
    const int tid = threadIdx.x;
    const int wid = tid >> 5, lane = tid & 31;
    const int wm = (wid & 1) * 64;        // warp M offset
    const int wn = (wid >> 1) * 32;       // warp N offset
    const int grp = lane >> 2, tig = lane & 3;

    const int n0 = blockIdx.x * 128;
    const int m0 = blockIdx.y * 128;
    const int region = (n0 < DIM) ? 0 : (n0 >= 2 * DIM ? 1 : -1);
    const int nr = n0 - (region == 1 ? 2 * DIM : 0);
    const int total = (region >= 0) ? 78 : 72;
    const int per_pass = (region >= 0) ? 26 : 24;

    // per-thread load indices (2 A + 2 B rows x 16B chunks)
    const int l_row0 = tid >> 2,        l_c0 = (tid & 3);
    const int l_row1 = (tid + 256) >> 2, l_c1 = ((tid + 256) & 3);

    float acc[4][4][4];
    #pragma unroll
    for (int i = 0; i < 4; i++)
        #pragma unroll
        for (int j = 0; j < 4; j++)
            #pragma unroll
            for (int k = 0; k < 4; k++) acc[i][j][k] = 0.f;

    // ---- job pointer computation ----
    auto job = [&](int idx, const __nv_bfloat16*& A, const __nv_bfloat16*& B,
                   int& rsa, int& rsb) {
        int pass = idx / per_pass;
        int r = idx - pass * per_pass;
        if (r < 24) {
            A = (pass < 2 ? g_xhi : g_xlo) + (size_t)m0 * DIM + r * 32;
            B = (pass == 1 ? g_wtlo : g_wthi) + (size_t)n0 * DIM + r * 32;
            rsa = DIM; rsb = DIM;
        } else {
            int rr = r - 24;
            A = (pass < 2 ? (region == 0 ? g_mqhi : g_mvhi)
                          : (region == 0 ? g_mqlo : g_mvlo))
                + (size_t)m0 * KPAD + rr * 32;
            B = (pass == 1 ? (region == 0 ? g_wbtq_lo : g_wbtv_lo)
                           : (region == 0 ? g_wbtq_hi : g_wbtv_hi))
                + (size_t)nr * KPAD + rr * 32;
            rsa = KPAD; rsb = KPAD;
        }
    };

    auto load_chunk = [&](int idx) {
        const __nv_bfloat16 *A, *B;
        int rsa, rsb;
        job(idx, A, B, rsa, rsb);
        const uint32_t sa = sbase + (uint32_t)(idx & (STAGES - 1)) * STAGE_BYTES;
        const uint32_t sb = sa + STAGE_A_BYTES;
        cp16(sa + (uint32_t)(l_row0 * 80 + l_c0 * 16), A + (size_t)l_row0 * rsa + l_c0 * 8);
        cp16(sa + (uint32_t)(l_row1 * 80 + l_c1 * 16), A + (size_t)l_row1 * rsa + l_c1 * 8);
        cp16(sb + (uint32_t)(l_row0 * 80 + l_c0 * 16), B + (size_t)l_row0 * rsb + l_c0 * 8);
        cp16(sb + (uint32_t)(l_row1 * 80 + l_c1 * 16), B + (size_t)l_row1 * rsb + l_c1 * 8);
        asm volatile("cp.async.commit_group;");
    };

    // prologue: fill pipeline
    #pragma unroll
    for (int s = 0; s < STAGES - 1; s++) load_chunk(s);

    // ldmatrix address components (fixed per thread)
    const uint32_t a_row = (uint32_t)(wm + (lane & 15));
    const uint32_t a_kof = (uint32_t)((lane >> 4) * 8);
    const uint32_t b_row = (uint32_t)(wn + (lane & 7) + ((lane >> 4) * 8));
    const uint32_t b_kof = (uint32_t)(((lane >> 3) & 1) * 8);

    for (int i = 0; i < total; i++) {
        asm volatile("cp.async.wait_group %0;" :: "n"(STAGES - 2));
        __syncthreads();
        if (i + STAGES - 1 < total) load_chunk(i + STAGES - 1);

        const uint32_t aBase = sbase + (uint32_t)(i & (STAGES - 1)) * STAGE_BYTES;
        const uint32_t bBase = aBase + STAGE_A_BYTES;

        #pragma unroll
        for (int ks = 0; ks < 2; ks++) {
            uint32_t a[4][4], b[4][2];
            #pragma unroll
            for (int mi = 0; mi < 4; mi++) {
                uint32_t ad = aBase + ((a_row + mi * 16) * APITCH + ks * 16 + a_kof) * 2;
                ldm_x4(ad, a[mi][0], a[mi][1], a[mi][2], a[mi][3]);
            }
            #pragma unroll
            for (int nj = 0; nj < 2; nj++) {
                uint32_t bd = bBase + ((b_row + nj * 16) * APITCH + ks * 16 + b_kof) * 2;
                ldm_x4(bd, b[nj * 2][0], b[nj * 2][1], b[nj * 2 + 1][0], b[nj * 2 + 1][1]);
            }
            #pragma unroll
            for (int mi = 0; mi < 4; mi++)
                #pragma unroll
                for (int ni = 0; ni < 4; ni++)
                    mma16816(acc[mi][ni], a[mi], b[ni]);
        }
        __syncthreads();
    }

    // epilogue: C frag c0,c1 -> row grp, cols 2*tig,+1 ; c2,c3 -> row grp+8
    #pragma unroll
    for (int ni = 0; ni < 4; ni++) {
        const int n = n0 + wn + ni * 8 + 2 * tig;
        const float2 bv = *(const float2*)&bqkv[n];
        #pragma unroll
        for (int mi = 0; mi < 4; mi++) {
            const int m = m0 + wm + mi * 16 + grp;
            float2 v0 = make_float2(acc[mi][ni][0] + bv.x, acc[mi][ni][1] + bv.y);
            float2 v1 = make_float2(acc[mi][ni][2] + bv.x, acc[mi][ni][3] + bv.y);
            *(float2*)&out[(size_t)m * MOUT + n] = v0;
            *(float2*)&out[(size_t)(m + 8) * MOUT + n] = v1;
        }
    }
}

// ---------------------------------------------------------------------------
extern "C" void kernel_launch(void* const* d_in, const int* in_sizes, int n_in,
                              void* d_out, int out_size) {
    const float* x     = (const float*)d_in[0];
    const float* W_qkv = (const float*)d_in[1];
    const float* b_qkv = (const float*)d_in[2];
    const float* Wa_q  = (const float*)d_in[3];
    const float* Wb_q  = (const float*)d_in[4];
    const float* Wa_v  = (const float*)d_in[5];
    const float* Wb_v  = (const float*)d_in[6];
    const float* K_q3  = (const float*)d_in[7];
    const float* b_q3  = (const float*)d_in[8];
    const float* K_v3  = (const float*)d_in[9];
    const float* b_v3  = (const float*)d_in[10];
    const float* K_q1  = (const float*)d_in[11];
    const float* b_q1  = (const float*)d_in[12];
    const float* K_v1  = (const float*)d_in[13];
    const float* b_v1  = (const float*)d_in[14];
    float* out = (float*)d_out;

    cudaFuncSetAttribute(k_mma, cudaFuncAttributeMaxDynamicSharedMemorySize,
                         SMEM_TOTAL);

    k_split_x<<<NPIX * DIM / 8 / 256, 256>>>(x);
    k_split_w<<<dim3(MOUT / 32, DIM / 32), 256>>>(W_qkv);
    k_split_wb<<<dim3(DIM * KPAD / 256, 2), 256>>>(Wb_q, Wb_v);
    k_down<<<NPIX / 32, 256>>>(x, Wa_q, Wa_v);
    k_conv<<<dim3(WW / 16, (HH / 16) * NB, 2), 256>>>(K_q3, b_q3, K_v3, b_v3,
                                                      K_q1, b_q1, K_v1, b_v1);
    k_mma<<<dim3(MOUT / 128, NPIX / 128), 256, SMEM_TOTAL>>>(b_qkv, out);
}

// round 4
// speedup vs baseline: 6.1855x; 3.1049x over previous
#include <cuda_runtime.h>
#include <cuda_fp16.h>
#include <cstdint>

#define NB 8
#define HH 64
#define WW 64
#define DIM 768
#define RR 16
#define NPIX 32768
#define MOUT 2304
#define KP 32

#define STAGES 4
#define APITCH 40                        // halves per smem row (32 data + 8 pad)
#define STAGE_A_BYTES (128 * APITCH * 2) // 10240
#define STAGE_BYTES (2 * STAGE_A_BYTES)  // 20480
#define SMEM_MMA (STAGES * STAGE_BYTES)  // 81920

#define WPITCH 776                       // k_prep W smem pitch (768 + 8)
#define SW_BYTES (32 * WPITCH * 2)       // 49664
#define SX_OFF SW_BYTES
#define SMEM_PREP (SW_BYTES + 128 * APITCH * 2)  // 59904

// ------------------------- scratch (device globals) -------------------------
__device__ __align__(256) __half g_xh[NPIX * DIM];    // x in fp16
__device__ __align__(256) __half g_wth[MOUT * DIM];   // W_qkv^T fp16 [n][k]
__device__ __align__(256) float  g_aq[NPIX * RR];
__device__ __align__(256) float  g_av[NPIX * RR];
__device__ __align__(256) __half g_mqh[NPIX * KP];    // mid_q fp16, K padded 16->32
__device__ __align__(256) __half g_mvh[NPIX * KP];
__device__ __align__(256) __half g_wbtq[DIM * KP];    // Wb_q^T fp16 padded [n][k]
__device__ __align__(256) __half g_wbtv[DIM * KP];

// ------------------------------ helpers -------------------------------------
__device__ __forceinline__ uint32_t smem_u32(const void* p) {
    uint32_t a;
    asm("{ .reg .u64 t; cvta.to.shared.u64 t, %1; cvt.u32.u64 %0, t; }" : "=r"(a) : "l"(p));
    return a;
}

__device__ __forceinline__ void cp16(uint32_t dst, const void* src) {
    asm volatile("cp.async.cg.shared.global [%0], [%1], 16;" :: "r"(dst), "l"(src));
}

__device__ __forceinline__ void ldm_x4(uint32_t addr, uint32_t& r0, uint32_t& r1,
                                       uint32_t& r2, uint32_t& r3) {
    asm volatile("ldmatrix.sync.aligned.m8n8.x4.shared.b16 {%0,%1,%2,%3}, [%4];"
                 : "=r"(r0), "=r"(r1), "=r"(r2), "=r"(r3) : "r"(addr));
}

__device__ __forceinline__ void mma16816(float* c, const uint32_t* a, const uint32_t* b) {
    asm volatile(
        "mma.sync.aligned.m16n8k16.row.col.f32.f16.f16.f32 "
        "{%0,%1,%2,%3}, {%4,%5,%6,%7}, {%8,%9}, {%0,%1,%2,%3};"
        : "+f"(c[0]), "+f"(c[1]), "+f"(c[2]), "+f"(c[3])
        : "r"(a[0]), "r"(a[1]), "r"(a[2]), "r"(a[3]), "r"(b[0]), "r"(b[1]));
}

// ---------------------------------------------------------------------------
// k_prep: fused  (a) x -> fp16 into g_xh   (b) a_q = x@Wa_q, a_v = x@Wa_v via HMMA
// 256 CTAs x 128 rows. W (768x32 fused q|v) transposed into smem once.
// ---------------------------------------------------------------------------
__global__ void __launch_bounds__(256) k_prep(const float* __restrict__ x,
                                              const float* __restrict__ Wa_q,
                                              const float* __restrict__ Wa_v) {
    extern __shared__ char sm[];
    __half* sW = (__half*)sm;             // [n=32][k=768] pitch WPITCH
    __half* sX = (__half*)(sm + SX_OFF);  // [128][32] pitch APITCH
    const uint32_t sbase = smem_u32(sm);
    const int tid = threadIdx.x;
    const int wid = tid >> 5, lane = tid & 31;
    const int m0 = blockIdx.x * 128;

    for (int i = tid; i < DIM * 32; i += 256) {
        int k = i >> 5, n = i & 31;
        float v = (n < 16) ? Wa_q[k * RR + n] : Wa_v[k * RR + (n - 16)];
        sW[n * WPITCH + k] = __float2half_rn(v);
    }

    const int row = tid >> 1;
    const int hs = tid & 1;

    float acc[4][4];
    #pragma unroll
    for (int i = 0; i < 4; i++)
        #pragma unroll
        for (int j = 0; j < 4; j++) acc[i][j] = 0.f;

    const uint32_t a_row = (uint32_t)(wid * 16 + (lane & 15));
    const uint32_t a_k8  = (uint32_t)((lane >> 4) * 8);
    const uint32_t b_row = (uint32_t)((lane & 7) + ((lane >> 4) * 8));
    const uint32_t b_k8  = (uint32_t)(((lane >> 3) & 1) * 8);

    for (int kb = 0; kb < 24; kb++) {
        const float* src = x + (size_t)(m0 + row) * DIM + kb * 32 + hs * 16;
        float4 f0 = *(const float4*)(src);
        float4 f1 = *(const float4*)(src + 4);
        float4 f2 = *(const float4*)(src + 8);
        float4 f3 = *(const float4*)(src + 12);
        __half h[16];
        h[0] = __float2half_rn(f0.x);  h[1] = __float2half_rn(f0.y);
        h[2] = __float2half_rn(f0.z);  h[3] = __float2half_rn(f0.w);
        h[4] = __float2half_rn(f1.x);  h[5] = __float2half_rn(f1.y);
        h[6] = __float2half_rn(f1.z);  h[7] = __float2half_rn(f1.w);
        h[8] = __float2half_rn(f2.x);  h[9] = __float2half_rn(f2.y);
        h[10] = __float2half_rn(f2.z); h[11] = __float2half_rn(f2.w);
        h[12] = __float2half_rn(f3.x); h[13] = __float2half_rn(f3.y);
        h[14] = __float2half_rn(f3.z); h[15] = __float2half_rn(f3.w);

        __half* gx = g_xh + (size_t)(m0 + row) * DIM + kb * 32 + hs * 16;
        *(uint4*)gx = ((uint4*)h)[0];
        *(uint4*)(gx + 8) = ((uint4*)h)[1];
        __half* sx = sX + row * APITCH + hs * 16;
        *(uint4*)sx = ((uint4*)h)[0];
        *(uint4*)(sx + 8) = ((uint4*)h)[1];
        __syncthreads();

        #pragma unroll
        for (int ks = 0; ks < 2; ks++) {
            uint32_t a[4];
            uint32_t ad = sbase + SX_OFF + (a_row * APITCH + ks * 16 + a_k8) * 2;
            ldm_x4(ad, a[0], a[1], a[2], a[3]);
            uint32_t b[4][2];
            #pragma unroll
            for (int nj = 0; nj < 2; nj++) {
                uint32_t bd = sbase +
                    ((b_row + nj * 16) * WPITCH + kb * 32 + ks * 16 + b_k8) * 2;
                ldm_x4(bd, b[nj * 2][0], b[nj * 2][1],
                       b[nj * 2 + 1][0], b[nj * 2 + 1][1]);
            }
            #pragma unroll
            for (int nj = 0; nj < 4; nj++) mma16816(acc[nj], a, b[nj]);
        }
        __syncthreads();
    }

    const int grp = lane >> 2, tig = lane & 3;
    const int r0 = m0 + wid * 16 + grp;
    #pragma unroll
    for (int nj = 0; nj < 4; nj++) {
        int n = nj * 8 + 2 * tig;
        float* o = (n < 16) ? g_aq : g_av;
        int nn = n & 15;
        *(float2*)&o[(size_t)r0 * RR + nn] = make_float2(acc[nj][0], acc[nj][1]);
        *(float2*)&o[(size_t)(r0 + 8) * RR + nn] = make_float2(acc[nj][2], acc[nj][3]);
    }
}

// ---------------------------------------------------------------------------
// W_qkv [768][2304] -> transposed fp16 [2304][768]
// ---------------------------------------------------------------------------
__global__ void k_wt(const float* __restrict__ W) {
    __shared__ float t[32][33];
    const int bx = blockIdx.x;           // MOUT/32 = 72
    const int by = blockIdx.y;           // DIM/32 = 24
    const int tx = threadIdx.x & 31, ty = threadIdx.x >> 5;
    #pragma unroll
    for (int k = 0; k < 4; k++) {
        int r = by * 32 + ty + k * 8;
        t[ty + k * 8][tx] = W[(size_t)r * MOUT + bx * 32 + tx];
    }
    __syncthreads();
    #pragma unroll
    for (int k = 0; k < 4; k++) {
        int n = bx * 32 + ty + k * 8;
        g_wth[(size_t)n * DIM + by * 32 + tx] = __float2half_rn(t[tx][ty + k * 8]);
    }
}

// ---------------------------------------------------------------------------
// Wb [16][768] -> transposed padded fp16 [768][32]
// ---------------------------------------------------------------------------
__global__ void k_wbt(const float* __restrict__ Wb_q,
                      const float* __restrict__ Wb_v) {
    const int qv = blockIdx.y;
    const float* Wb = qv ? Wb_v : Wb_q;
    __half* oh = qv ? g_wbtv : g_wbtq;
    int i = blockIdx.x * 256 + threadIdx.x;   // DIM*KP = 24576
    int n = i >> 5, k = i & 31;
    oh[i] = __float2half_rn((k < RR) ? Wb[k * DIM + n] : 0.f);
}

// ---------------------------------------------------------------------------
// mid = conv3x3 + b3 + conv1x1 + b1 + identity; output fp16, K padded to 32
// ---------------------------------------------------------------------------
__global__ void k_conv(const float* __restrict__ K_q3, const float* __restrict__ b_q3,
                       const float* __restrict__ K_v3, const float* __restrict__ b_v3,
                       const float* __restrict__ K_q1, const float* __restrict__ b_q1,
                       const float* __restrict__ K_v1, const float* __restrict__ b_v1) {
    __shared__ float sh[18 * 18 * 17];
    __shared__ float sK3[9 * RR * RR];
    __shared__ float sK1[RR * RR];
    __shared__ float sb[RR];

    const int qv = blockIdx.z;
    const float* __restrict__ a  = qv == 0 ? g_aq : g_av;
    const float* __restrict__ K3 = qv == 0 ? K_q3 : K_v3;
    const float* __restrict__ K1 = qv == 0 ? K_q1 : K_v1;
    const float* __restrict__ b3 = qv == 0 ? b_q3 : b_v3;
    const float* __restrict__ b1 = qv == 0 ? b_q1 : b_v1;
    __half* __restrict__ mh = qv == 0 ? g_mqh : g_mvh;

    const int tile_x = blockIdx.x * 16;
    const int img    = blockIdx.y >> 2;
    const int tile_y = (blockIdx.y & 3) * 16;
    const int tid = threadIdx.x;

    for (int i = tid; i < 9 * RR * RR; i += 256) sK3[i] = K3[i];
    for (int i = tid; i < RR * RR; i += 256) sK1[i] = K1[i];
    if (tid < RR) sb[tid] = b3[tid] + b1[tid];

    for (int i = tid; i < 18 * 18 * 16; i += 256) {
        int c = i & 15;
        int p = i >> 4;
        int ww = p % 18, hh = p / 18;
        int h = tile_y + hh - 1, w = tile_x + ww - 1;
        float v = 0.f;
        if (h >= 0 && h < HH && w >= 0 && w < WW)
            v = a[(((img * HH + h) * WW) + w) * RR + c];
        sh[(hh * 18 + ww) * 17 + c] = v;
    }
    __syncthreads();

    const int ty = tid >> 4, tx = tid & 15;
    float acc[RR];
    const float* center = &sh[((ty + 1) * 18 + (tx + 1)) * 17];
    #pragma unroll
    for (int co = 0; co < RR; co++) acc[co] = sb[co] + center[co];

    #pragma unroll
    for (int ci = 0; ci < RR; ci++) {
        float v = center[ci];
        #pragma unroll
        for (int co = 0; co < RR; co++) acc[co] += v * sK1[ci * RR + co];
    }
    #pragma unroll
    for (int kh = 0; kh < 3; kh++) {
        #pragma unroll
        for (int kw = 0; kw < 3; kw++) {
            const float* p  = &sh[((ty + kh) * 18 + (tx + kw)) * 17];
            const float* kk = &sK3[(kh * 3 + kw) * RR * RR];
            #pragma unroll
            for (int ci = 0; ci < RR; ci++) {
                float v = p[ci];
                #pragma unroll
                for (int co = 0; co < RR; co++) acc[co] += v * kk[ci * RR + co];
            }
        }
    }

    const int h = tile_y + ty, w = tile_x + tx;
    const int pix = ((img * HH + h) * WW) + w;
    __half hb[RR];
    #pragma unroll
    for (int co = 0; co < RR; co++) hb[co] = __float2half_rn(acc[co]);
    uint4* oh = (uint4*)(mh + (size_t)pix * KP);
    oh[0] = ((uint4*)hb)[0];
    oh[1] = ((uint4*)hb)[1];
    uint4 z = make_uint4(0, 0, 0, 0);
    oh[2] = z;
    oh[3] = z;
}

// ---------------------------------------------------------------------------
// Main HMMA GEMM (single-pass fp16, fp32 accumulate):
// out[32768,2304] = x_fp16 @ W^T_fp16 + LoRA chunk + bias
// 128x128 tile, BK=32, 4-stage cp.async, 8 warps (64x32), single sync/iter.
// ---------------------------------------------------------------------------
__global__ void __launch_bounds__(256) k_mma(const float* __restrict__ bqkv,
                                             float* __restrict__ out) {
    extern __shared__ char smem[];
    const uint32_t sbase = smem_u32(smem);
    const int tid = threadIdx.x;
    const int wid = tid >> 5, lane = tid & 31;
    const int wm = (wid & 1) * 64;
    const int wn = (wid >> 1) * 32;
    const int grp = lane >> 2, tig = lane & 3;

    const int n0 = blockIdx.x * 128;
    const int m0 = blockIdx.y * 128;
    const int region = (n0 < DIM) ? 0 : (n0 >= 2 * DIM ? 1 : -1);
    const int nr = n0 - (region == 1 ? 2 * DIM : 0);
    const int total = (region >= 0) ? 25 : 24;

    const int l_row0 = tid >> 2,         l_c0 = (tid & 3);
    const int l_row1 = (tid + 256) >> 2, l_c1 = ((tid + 256) & 3);

    float acc[4][4][4];
    #pragma unroll
    for (int i = 0; i < 4; i++)
        #pragma unroll
        for (int j = 0; j < 4; j++)
            #pragma unroll
            for (int k = 0; k < 4; k++) acc[i][j][k] = 0.f;

    auto job = [&](int idx, const __half*& A, const __half*& B, int& rsa, int& rsb) {
        if (idx < 24) {
            A = g_xh + (size_t)m0 * DIM + idx * 32;
            B = g_wth + (size_t)n0 * DIM + idx * 32;
            rsa = DIM; rsb = DIM;
        } else {
            A = (region == 0 ? g_mqh : g_mvh) + (size_t)m0 * KP;
            B = (region == 0 ? g_wbtq : g_wbtv) + (size_t)nr * KP;
            rsa = KP; rsb = KP;
        }
    };

    auto load_chunk = [&](int idx) {
        const __half *A, *B;
        int rsa, rsb;
        job(idx, A, B, rsa, rsb);
        const uint32_t sa = sbase + (uint32_t)(idx & (STAGES - 1)) * STAGE_BYTES;
        const uint32_t sb = sa + STAGE_A_BYTES;
        cp16(sa + (uint32_t)(l_row0 * 80 + l_c0 * 16), A + (size_t)l_row0 * rsa + l_c0 * 8);
        cp16(sa + (uint32_t)(l_row1 * 80 + l_c1 * 16), A + (size_t)l_row1 * rsa + l_c1 * 8);
        cp16(sb + (uint32_t)(l_row0 * 80 + l_c0 * 16), B + (size_t)l_row0 * rsb + l_c0 * 8);
        cp16(sb + (uint32_t)(l_row1 * 80 + l_c1 * 16), B + (size_t)l_row1 * rsb + l_c1 * 8);
        asm volatile("cp.async.commit_group;");
    };

    #pragma unroll
    for (int s = 0; s < STAGES - 1; s++) load_chunk(s);

    const uint32_t a_row = (uint32_t)(wm + (lane & 15));
    const uint32_t a_kof = (uint32_t)((lane >> 4) * 8);
    const uint32_t b_row = (uint32_t)(wn + (lane & 7) + ((lane >> 4) * 8));
    const uint32_t b_kof = (uint32_t)(((lane >> 3) & 1) * 8);

    for (int i = 0; i < total; i++) {
        asm volatile("cp.async.wait_group %0;" :: "n"(STAGES - 2));
        __syncthreads();
        if (i + STAGES - 1 < total) load_chunk(i + STAGES - 1);

        const uint32_t aBase = sbase + (uint32_t)(i & (STAGES - 1)) * STAGE_BYTES;
        const uint32_t bBase = aBase + STAGE_A_BYTES;

        #pragma unroll
        for (int ks = 0; ks < 2; ks++) {
            uint32_t a[4][4], b[4][2];
            #pragma unroll
            for (int mi = 0; mi < 4; mi++) {
                uint32_t ad = aBase + ((a_row + mi * 16) * APITCH + ks * 16 + a_kof) * 2;
                ldm_x4(ad, a[mi][0], a[mi][1], a[mi][2], a[mi][3]);
            }
            #pragma unroll
            for (int nj = 0; nj < 2; nj++) {
                uint32_t bd = bBase + ((b_row + nj * 16) * APITCH + ks * 16 + b_kof) * 2;
                ldm_x4(bd, b[nj * 2][0], b[nj * 2][1], b[nj * 2 + 1][0], b[nj * 2 + 1][1]);
            }
            #pragma unroll
            for (int mi = 0; mi < 4; mi++)
                #pragma unroll
                for (int ni = 0; ni < 4; ni++)
                    mma16816(acc[mi][ni], a[mi], b[ni]);
        }
    }

    #pragma unroll
    for (int ni = 0; ni < 4; ni++) {
        const int n = n0 + wn + ni * 8 + 2 * tig;
        const float2 bv = *(const float2*)&bqkv[n];
        #pragma unroll
        for (int mi = 0; mi < 4; mi++) {
            const int m = m0 + wm + mi * 16 + grp;
            float2 v0 = make_float2(acc[mi][ni][0] + bv.x, acc[mi][ni][1] + bv.y);
            float2 v1 = make_float2(acc[mi][ni][2] + bv.x, acc[mi][ni][3] + bv.y);
            *(float2*)&out[(size_t)m * MOUT + n] = v0;
            *(float2*)&out[(size_t)(m + 8) * MOUT + n] = v1;
        }
    }
}

// ---------------------------------------------------------------------------
extern "C" void kernel_launch(void* const* d_in, const int* in_sizes, int n_in,
                              void* d_out, int out_size) {
    const float* x     = (const float*)d_in[0];
    const float* W_qkv = (const float*)d_in[1];
    const float* b_qkv = (const float*)d_in[2];
    const float* Wa_q  = (const float*)d_in[3];
    const float* Wb_q  = (const float*)d_in[4];
    const float* Wa_v  = (const float*)d_in[5];
    const float* Wb_v  = (const float*)d_in[6];
    const float* K_q3  = (const float*)d_in[7];
    const float* b_q3  = (const float*)d_in[8];
    const float* K_v3  = (const float*)d_in[9];
    const float* b_v3  = (const float*)d_in[10];
    const float* K_q1  = (const float*)d_in[11];
    const float* b_q1  = (const float*)d_in[12];
    const float* K_v1  = (const float*)d_in[13];
    const float* b_v1  = (const float*)d_in[14];
    float* out = (float*)d_out;

    cudaFuncSetAttribute(k_prep, cudaFuncAttributeMaxDynamicSharedMemorySize, SMEM_PREP);
    cudaFuncSetAttribute(k_mma, cudaFuncAttributeMaxDynamicSharedMemorySize, SMEM_MMA);

    k_prep<<<NPIX / 128, 256, SMEM_PREP>>>(x, Wa_q, Wa_v);
    k_wt<<<dim3(MOUT / 32, DIM / 32), 256>>>(W_qkv);
    k_wbt<<<dim3(DIM * KP / 256, 2), 256>>>(Wb_q, Wb_v);
    k_conv<<<dim3(WW / 16, (HH / 16) * NB, 2), 256>>>(K_q3, b_q3, K_v3, b_v3,
                                                      K_q1, b_q1, K_v1, b_v1);
    k_mma<<<dim3(MOUT / 128, NPIX / 128), 256, SMEM_MMA>>>(b_qkv, out);
}